// round 4
// baseline (speedup 1.0000x reference)
#include <cuda_runtime.h>
#include <cstdint>

#define B_    2
#define H_    512
#define W_    512
#define NIN_  64
#define NOUT_ 64
#define NNZ_  131072
#define NMASK_ 131072
#define PTS_PER_CTA 64

// 2 MB mask scratch (allowed: __device__ global, no runtime alloc)
__device__ float g_mask[B_ * H_ * W_];
__device__ int   g_is64;

// ---------------------------------------------------------------------------
// Detect whether the index tensors are int64 or int32.
// int64 little-endian: words at odd positions are the high halves of small
// nonnegative values -> all zero. int32: odd words are y/x/b coords, almost
// surely not all zero across 64 samples. Deterministic per input.
// ---------------------------------------------------------------------------
__global__ void detect_idx_dtype_kernel(const unsigned int* __restrict__ w) {
    __shared__ int any_nonzero;
    if (threadIdx.x == 0) any_nonzero = 0;
    __syncthreads();
    unsigned int v = w[threadIdx.x * 2 + 1];   // first 64 odd words
    if (v != 0u) atomicOr(&any_nonzero, 1);
    __syncthreads();
    if (threadIdx.x == 0) g_is64 = (any_nonzero == 0) ? 1 : 0;
}

__device__ __forceinline__ int3 load_triplet(const void* p, int i, int is64) {
    if (is64) {
        const long long* q = (const long long*)p;
        return make_int3((int)q[3 * i], (int)q[3 * i + 1], (int)q[3 * i + 2]);
    } else {
        const int* q = (const int*)p;
        return make_int3(q[3 * i], q[3 * i + 1], q[3 * i + 2]);
    }
}

// ---------------------------------------------------------------------------
// Mask scatter: g_mask[b,y,x] += mask_values[i]
// ---------------------------------------------------------------------------
__global__ void mask_scatter_kernel(const void* __restrict__ mask_idx,
                                    const float* __restrict__ mask_vals) {
    int i = blockIdx.x * blockDim.x + threadIdx.x;
    if (i >= NMASK_) return;
    int is64 = g_is64;
    int3 t = load_triplet(mask_idx, i, is64);
    atomicAdd(&g_mask[(t.x * H_ + t.y) * W_ + t.z], mask_vals[i]);
}

// ---------------------------------------------------------------------------
// Vectorized global reduction add (sm_90+ PTX)
// ---------------------------------------------------------------------------
__device__ __forceinline__ void red_add_v4(float* p, float4 v) {
    asm volatile("red.global.add.v4.f32 [%0], {%1, %2, %3, %4};"
                 :: "l"(p), "f"(v.x), "f"(v.y), "f"(v.z), "f"(v.w)
                 : "memory");
}

// ---------------------------------------------------------------------------
// Main sparse conv: grid = (NNZ/64, 3[ky]), block = 256.
// Each thread: 4 points x 4 channels x 3 kx-taps (48 FMA / k-iter).
// SMEM: weights[3][64][64] (48KB) + valuesT[64][68] (17KB) + idx[64][3]
// ---------------------------------------------------------------------------
__global__ void conv_scatter_kernel(const float* __restrict__ values,
                                    const float* __restrict__ kern,
                                    const void*  __restrict__ indices,
                                    float* __restrict__ out) {
    extern __shared__ float smem[];
    float* sW = smem;                        // [kx][k][c] : 3*64*64
    float* sV = smem + 3 * 64 * 64;          // [k][p] padded rows of 68
    int*   sI = (int*)(sV + 64 * 68);        // [p][3] : b, sy(clipped), ix

    const int t  = threadIdx.x;
    const int ky = blockIdx.y;

    // Stage weights for this ky: 12288 floats = 3072 float4, 256 threads
    {
        const float4* gW = (const float4*)(kern + (size_t)ky * 3 * 64 * 64);
        float4* sW4 = (float4*)sW;
        #pragma unroll
        for (int r = 0; r < 12; r++) sW4[r * 256 + t] = gW[r * 256 + t];
    }

    const int gp0 = blockIdx.x * PTS_PER_CTA;

    // Stage values transposed: sV[k][p] (pad 68 keeps 16B alignment of rows)
    #pragma unroll
    for (int r = 0; r < 4; r++) {
        int li = r * 1024 + t * 4;            // flat offset into 64x64 tile
        int p = li >> 6, k = li & 63;
        float4 v = *(const float4*)(values + (size_t)gp0 * 64 + li);
        sV[(k + 0) * 68 + p] = v.x;
        sV[(k + 1) * 68 + p] = v.y;
        sV[(k + 2) * 68 + p] = v.z;
        sV[(k + 3) * 68 + p] = v.w;
    }

    // Stage indices with ky-row clip precomputed
    if (t < PTS_PER_CTA) {
        int is64 = g_is64;
        int3 tr = load_triplet(indices, gp0 + t, is64);
        int sy = tr.y + ky - 1;
        sy = min(max(sy, 0), H_ - 1);
        sI[t * 3 + 0] = tr.x;
        sI[t * 3 + 1] = sy;
        sI[t * 3 + 2] = tr.z;
    }
    __syncthreads();

    const int c4 = (t & 15) * 4;        // channel quad
    const int pb = (t >> 4) * 4;        // point quad base

    float4 acc[4][3];
    #pragma unroll
    for (int j = 0; j < 4; j++)
        #pragma unroll
        for (int kx = 0; kx < 3; kx++)
            acc[j][kx] = make_float4(0.f, 0.f, 0.f, 0.f);

    #pragma unroll 4
    for (int k = 0; k < 64; k++) {
        float4 v  = *(float4*)&sV[k * 68 + pb];
        float4 w0 = *(float4*)&sW[(0 * 64 + k) * 64 + c4];
        float4 w1 = *(float4*)&sW[(1 * 64 + k) * 64 + c4];
        float4 w2 = *(float4*)&sW[(2 * 64 + k) * 64 + c4];
        float vv[4] = {v.x, v.y, v.z, v.w};
        #pragma unroll
        for (int j = 0; j < 4; j++) {
            float vj = vv[j];
            acc[j][0].x = fmaf(vj, w0.x, acc[j][0].x);
            acc[j][0].y = fmaf(vj, w0.y, acc[j][0].y);
            acc[j][0].z = fmaf(vj, w0.z, acc[j][0].z);
            acc[j][0].w = fmaf(vj, w0.w, acc[j][0].w);
            acc[j][1].x = fmaf(vj, w1.x, acc[j][1].x);
            acc[j][1].y = fmaf(vj, w1.y, acc[j][1].y);
            acc[j][1].z = fmaf(vj, w1.z, acc[j][1].z);
            acc[j][1].w = fmaf(vj, w1.w, acc[j][1].w);
            acc[j][2].x = fmaf(vj, w2.x, acc[j][2].x);
            acc[j][2].y = fmaf(vj, w2.y, acc[j][2].y);
            acc[j][2].z = fmaf(vj, w2.z, acc[j][2].z);
            acc[j][2].w = fmaf(vj, w2.w, acc[j][2].w);
        }
    }

    // Scatter: 3 taps x 4 points, red.v4 per channel quad
    #pragma unroll
    for (int j = 0; j < 4; j++) {
        int p  = pb + j;
        int b  = sI[p * 3 + 0];
        int sy = sI[p * 3 + 1];
        int ix = sI[p * 3 + 2];
        int rowbase = (b * H_ + sy) * W_;
        #pragma unroll
        for (int kx = 0; kx < 3; kx++) {
            int sx = ix + kx - 1;
            sx = min(max(sx, 0), W_ - 1);
            float* dst = out + ((size_t)(rowbase + sx) * NOUT_ + c4);
            red_add_v4(dst, acc[j][kx]);
        }
    }
}

// ---------------------------------------------------------------------------
// Epilogue: out = (dense + mask*bias) * mask, float4-vectorized
// ---------------------------------------------------------------------------
__global__ void finalize_kernel(float* __restrict__ out,
                                const float* __restrict__ bias) {
    int i = blockIdx.x * blockDim.x + threadIdx.x;   // float4 index
    int pix = i >> 4;
    int c4  = (i & 15) * 4;
    float m = g_mask[pix];
    float4 o = ((float4*)out)[i];
    float4 bb = *(const float4*)(bias + c4);
    o.x = (o.x + m * bb.x) * m;
    o.y = (o.y + m * bb.y) * m;
    o.z = (o.z + m * bb.z) * m;
    o.w = (o.w + m * bb.w) * m;
    ((float4*)out)[i] = o;
}

// ---------------------------------------------------------------------------
extern "C" void kernel_launch(void* const* d_in, const int* in_sizes, int n_in,
                              void* d_out, int out_size) {
    const float* values    = (const float*)d_in[0];
    const float* kern      = (const float*)d_in[1];
    const float* bias      = (const float*)d_in[2];
    const float* mask_vals = (const float*)d_in[3];
    const void*  indices   = d_in[4];
    const void*  mask_idx  = d_in[5];
    float* out = (float*)d_out;

    void* maskPtr = nullptr;
    cudaGetSymbolAddress(&maskPtr, g_mask);

    size_t smem = (3 * 64 * 64 + 64 * 68) * sizeof(float) + 64 * 3 * sizeof(int);
    cudaFuncSetAttribute(conv_scatter_kernel,
                         cudaFuncAttributeMaxDynamicSharedMemorySize, (int)smem);

    cudaMemsetAsync(out, 0, (size_t)out_size * sizeof(float), 0);
    cudaMemsetAsync(maskPtr, 0, sizeof(float) * B_ * H_ * W_, 0);

    detect_idx_dtype_kernel<<<1, 64>>>((const unsigned int*)indices);
    mask_scatter_kernel<<<NMASK_ / 256, 256>>>(mask_idx, mask_vals);
    conv_scatter_kernel<<<dim3(NNZ_ / PTS_PER_CTA, 3), 256, smem>>>(
        values, kern, indices, out);
    finalize_kernel<<<(B_ * H_ * W_ * (NOUT_ / 4)) / 256, 256>>>(out, bias);
}